// round 1
// baseline (speedup 1.0000x reference)
#include <cuda_runtime.h>
#include <cuda_bf16.h>
#include <mma.h>

using namespace nvcuda;

// Problem constants
#define BATCH  4
#define SEQ    4096
#define DMODEL 1024
#define NHEAD  16
#define HDIM   64
#define DFF    4096
#define WIN    512
#define MROWS  (BATCH*SEQ)          // 16384

// ---------------- scratch (device globals; no allocations allowed) ----------
static __device__ float g_q   [(size_t)MROWS * DMODEL];
static __device__ float g_k   [(size_t)MROWS * DMODEL];
static __device__ float g_v   [(size_t)MROWS * DMODEL];
static __device__ float g_attn[(size_t)MROWS * DMODEL];
static __device__ float g_xln [(size_t)MROWS * DMODEL];
static __device__ float g_h   [(size_t)MROWS * DFF];
static __device__ float g_y   [(size_t)MROWS * DMODEL];

// ============================================================================
// Generic TN GEMM: C[M,N] = A[M,K] @ W[N,K]^T (+ epilogue)
//   MODE 0: +bias, scatter to [B,H,S,d] layout (QKV)
//   MODE 1: +bias, ReLU, row-major out (FFN1)
//   MODE 2: +bias, +extra (residual), row-major out (FFN2)
// Block: 256 threads (8 warps as 4m x 2n, each warp 32x32 via 2x2 m16n16k8)
// Tile: BM=128, BN=64, BK=32.  TF32 inputs, fp32 accumulate.
// ============================================================================
#define GBM 128
#define GBN 64
#define GBK 32
#define GLDA (GBK + 8)   // 40
#define GLDC (GBN + 4)   // 68

template <int MODE>
__global__ __launch_bounds__(256)
void gemm_tn(const float* __restrict__ A, const float* __restrict__ W,
             const float* __restrict__ bias, const float* __restrict__ extra,
             float* __restrict__ out, int K, int N)
{
    __shared__ float smem[GBM * GLDC];  // 8704 floats; aliased: [A|W] then C
    float* As = smem;                    // GBM*GLDA = 5120
    float* Ws = smem + GBM * GLDA;       // GBN*GLDA = 2560
    float* Cs = smem;

    const int tid = threadIdx.x;
    const int wid = tid >> 5;
    const int wm  = wid & 3;   // 0..3
    const int wn  = wid >> 2;  // 0..1

    wmma::fragment<wmma::accumulator, 16, 16, 8, float> acc[2][2];
#pragma unroll
    for (int i = 0; i < 2; i++)
#pragma unroll
        for (int j = 0; j < 2; j++)
            wmma::fill_fragment(acc[i][j], 0.0f);

    const float* Ablk = A + (size_t)blockIdx.y * GBM * K;
    const float* Wblk = W + (size_t)blockIdx.x * GBN * K;

    const int tr = tid >> 3;          // 0..31
    const int tc = (tid & 7) << 2;    // 0..28 step 4

    for (int kt = 0; kt < K; kt += GBK) {
        // load A tile 128x32
#pragma unroll
        for (int p = 0; p < 4; p++) {
            int r = tr + p * 32;
            *(float4*)(As + r * GLDA + tc) =
                *(const float4*)(Ablk + (size_t)r * K + kt + tc);
        }
        // load W tile 64x32
#pragma unroll
        for (int p = 0; p < 2; p++) {
            int r = tr + p * 32;
            *(float4*)(Ws + r * GLDA + tc) =
                *(const float4*)(Wblk + (size_t)r * K + kt + tc);
        }
        __syncthreads();

#pragma unroll
        for (int kk = 0; kk < GBK; kk += 8) {
            wmma::fragment<wmma::matrix_a, 16, 16, 8, wmma::precision::tf32, wmma::row_major> af[2];
            wmma::fragment<wmma::matrix_b, 16, 16, 8, wmma::precision::tf32, wmma::col_major> bf[2];
#pragma unroll
            for (int i = 0; i < 2; i++) {
                wmma::load_matrix_sync(af[i], As + (wm * 32 + i * 16) * GLDA + kk, GLDA);
#pragma unroll
                for (int t = 0; t < af[i].num_elements; t++)
                    af[i].x[t] = wmma::__float_to_tf32(af[i].x[t]);
            }
#pragma unroll
            for (int j = 0; j < 2; j++) {
                wmma::load_matrix_sync(bf[j], Ws + (wn * 32 + j * 16) * GLDA + kk, GLDA);
#pragma unroll
                for (int t = 0; t < bf[j].num_elements; t++)
                    bf[j].x[t] = wmma::__float_to_tf32(bf[j].x[t]);
            }
#pragma unroll
            for (int i = 0; i < 2; i++)
#pragma unroll
                for (int j = 0; j < 2; j++)
                    wmma::mma_sync(acc[i][j], af[i], bf[j], acc[i][j]);
        }
        __syncthreads();
    }

    // stage C through smem
#pragma unroll
    for (int i = 0; i < 2; i++)
#pragma unroll
        for (int j = 0; j < 2; j++)
            wmma::store_matrix_sync(Cs + (wm * 32 + i * 16) * GLDC + wn * 32 + j * 16,
                                    acc[i][j], GLDC, wmma::mem_row_major);
    __syncthreads();

    const int m0 = blockIdx.y * GBM;
    const int n0 = blockIdx.x * GBN;
    const int er = tid >> 4;           // 0..15
    const int ec = (tid & 15) << 2;    // 0..60 step 4

#pragma unroll
    for (int p = 0; p < 8; p++) {
        int r = er + p * 16;
        int m = m0 + r;
        float4 c = *(float4*)(Cs + r * GLDC + ec);
        float4 bb = *(const float4*)(bias + n0 + ec);
        c.x += bb.x; c.y += bb.y; c.z += bb.z; c.w += bb.w;
        if constexpr (MODE == 1) {
            c.x = fmaxf(c.x, 0.f); c.y = fmaxf(c.y, 0.f);
            c.z = fmaxf(c.z, 0.f); c.w = fmaxf(c.w, 0.f);
        }
        if constexpr (MODE == 2) {
            float4 e = *(const float4*)(extra + (size_t)m * N + n0 + ec);
            c.x += e.x; c.y += e.y; c.z += e.z; c.w += e.w;
        }
        if constexpr (MODE == 0) {
            // scatter to [B, H, S, d]
            int bi = m >> 12;          // /SEQ
            int s  = m & (SEQ - 1);
            int n  = n0 + ec;
            int h  = n >> 6;           // /HDIM
            int dd = n & (HDIM - 1);
            size_t o = (((size_t)bi * NHEAD + h) * SEQ + s) * HDIM + dd;
            *(float4*)(out + o) = c;
        } else {
            *(float4*)(out + (size_t)m * N + n0 + ec) = c;
        }
    }
}

// ============================================================================
// Windowed causal flash attention.
// Block = one (b, h, 64-row q chunk). 256 threads (8 warps as 2m x 4n for
// 64x64 wmma products). Online softmax over 64-key chunks.
// q/k/v in [B,H,S,d]; output written head-concat [B,S,D].
// ============================================================================
#define ALD 72          // padded row stride for 64-wide tiles
#define ACCLD 68

__global__ __launch_bounds__(256)
void attn_kernel(const float* __restrict__ q, const float* __restrict__ k,
                 const float* __restrict__ v, float* __restrict__ out)
{
    const int idx = blockIdx.x;
    const int qc = idx & 7;
    const int w  = (idx >> 3) & 7;
    const int h  = (idx >> 6) & 15;
    const int b  = idx >> 10;

    extern __shared__ float sm[];
    float* q_s  = sm;                  // 64*ALD
    float* k_s  = q_s + 64 * ALD;
    float* v_s  = k_s + 64 * ALD;
    float* s_s  = v_s + 64 * ALD;
    float* o_s  = s_s + 64 * ALD;
    float* accs = o_s + 64 * ALD;      // 64*ACCLD
    float* m_s  = accs + 64 * ACCLD;   // 64
    float* l_s  = m_s + 64;            // 64
    float* al_s = l_s + 64;            // 64

    const int tid = threadIdx.x;
    const size_t headbase = ((size_t)(b * NHEAD + h)) * SEQ * HDIM;
    const int q0 = w * WIN + qc * 64;  // global seq position of q chunk start

    const int tr = tid >> 4;           // 0..15
    const int tc = (tid & 15) << 2;    // 0..60 step 4

    // load q (scaled by d^-0.5 = 0.125), init acc/m/l
    const float* qg = q + headbase + (size_t)q0 * HDIM;
#pragma unroll
    for (int p = 0; p < 4; p++) {
        int r = tr + p * 16;
        float4 x = *(const float4*)(qg + r * HDIM + tc);
        x.x *= 0.125f; x.y *= 0.125f; x.z *= 0.125f; x.w *= 0.125f;
        *(float4*)(q_s + r * ALD + tc) = x;
        float4 z = make_float4(0.f, 0.f, 0.f, 0.f);
        *(float4*)(accs + r * ACCLD + tc) = z;
    }
    if (tid < 64) { m_s[tid] = -1e30f; l_s[tid] = 0.f; }
    __syncthreads();

    const int kstart = (w == 0) ? 0 : (w - 1) * WIN;
    const int kend   = q0 + 64;

    const int wid = tid >> 5;
    const int wm  = wid & 1;    // 0..1  (32 rows)
    const int wn  = wid >> 1;   // 0..3  (16 cols)

    for (int kc = kstart; kc < kend; kc += 64) {
        // load K, V chunks
        const float* kg = k + headbase + (size_t)kc * HDIM;
        const float* vg = v + headbase + (size_t)kc * HDIM;
#pragma unroll
        for (int p = 0; p < 4; p++) {
            int r = tr + p * 16;
            *(float4*)(k_s + r * ALD + tc) = *(const float4*)(kg + r * HDIM + tc);
            *(float4*)(v_s + r * ALD + tc) = *(const float4*)(vg + r * HDIM + tc);
        }
        __syncthreads();

        // S = q @ K^T  (64x64)
        {
            wmma::fragment<wmma::accumulator, 16, 16, 8, float> sacc[2];
#pragma unroll
            for (int i = 0; i < 2; i++) wmma::fill_fragment(sacc[i], 0.0f);
#pragma unroll
            for (int kk = 0; kk < HDIM; kk += 8) {
                wmma::fragment<wmma::matrix_a, 16, 16, 8, wmma::precision::tf32, wmma::row_major> af;
                wmma::fragment<wmma::matrix_b, 16, 16, 8, wmma::precision::tf32, wmma::col_major> bf;
                wmma::load_matrix_sync(bf, k_s + (wn * 16) * ALD + kk, ALD);
#pragma unroll
                for (int t = 0; t < bf.num_elements; t++) bf.x[t] = wmma::__float_to_tf32(bf.x[t]);
#pragma unroll
                for (int i = 0; i < 2; i++) {
                    wmma::load_matrix_sync(af, q_s + (wm * 32 + i * 16) * ALD + kk, ALD);
#pragma unroll
                    for (int t = 0; t < af.num_elements; t++) af.x[t] = wmma::__float_to_tf32(af.x[t]);
                    wmma::mma_sync(sacc[i], af, bf, sacc[i]);
                }
            }
#pragma unroll
            for (int i = 0; i < 2; i++)
                wmma::store_matrix_sync(s_s + (wm * 32 + i * 16) * ALD + wn * 16,
                                        sacc[i], ALD, wmma::mem_row_major);
        }
        __syncthreads();

        // online softmax: 4 lanes per row, 16 cols each
        {
            const bool diag = (kc == q0);
            const int r  = tid >> 2;           // 0..63
            const int c0 = (tid & 3) << 4;     // 0,16,32,48
            float* srow = s_s + r * ALD + c0;
            float mloc = -1e30f;
            if (diag) {
#pragma unroll
                for (int t = 0; t < 16; t++) {
                    float sv = srow[t];
                    if (c0 + t > r) sv = -1e30f;
                    srow[t] = sv;
                    mloc = fmaxf(mloc, sv);
                }
            } else {
#pragma unroll
                for (int t = 0; t < 16; t++) mloc = fmaxf(mloc, srow[t]);
            }
            mloc = fmaxf(mloc, __shfl_xor_sync(0xffffffffu, mloc, 1));
            mloc = fmaxf(mloc, __shfl_xor_sync(0xffffffffu, mloc, 2));
            float mold = m_s[r];
            float mnew = fmaxf(mold, mloc);
            float ssum = 0.f;
#pragma unroll
            for (int t = 0; t < 16; t++) {
                float pz = __expf(srow[t] - mnew);
                srow[t] = pz;
                ssum += pz;
            }
            ssum += __shfl_xor_sync(0xffffffffu, ssum, 1);
            ssum += __shfl_xor_sync(0xffffffffu, ssum, 2);
            float alpha = __expf(mold - mnew);  // underflows to 0 on first chunk
            if ((tid & 3) == 0) {
                m_s[r] = mnew;
                l_s[r] = l_s[r] * alpha + ssum;
                al_s[r] = alpha;
            }
        }
        __syncthreads();

        // O_chunk = P @ V  (64x64)
        {
            wmma::fragment<wmma::accumulator, 16, 16, 8, float> oacc[2];
#pragma unroll
            for (int i = 0; i < 2; i++) wmma::fill_fragment(oacc[i], 0.0f);
#pragma unroll
            for (int kk = 0; kk < 64; kk += 8) {
                wmma::fragment<wmma::matrix_a, 16, 16, 8, wmma::precision::tf32, wmma::row_major> af;
                wmma::fragment<wmma::matrix_b, 16, 16, 8, wmma::precision::tf32, wmma::row_major> bf;
                wmma::load_matrix_sync(bf, v_s + kk * ALD + wn * 16, ALD);
#pragma unroll
                for (int t = 0; t < bf.num_elements; t++) bf.x[t] = wmma::__float_to_tf32(bf.x[t]);
#pragma unroll
                for (int i = 0; i < 2; i++) {
                    wmma::load_matrix_sync(af, s_s + (wm * 32 + i * 16) * ALD + kk, ALD);
#pragma unroll
                    for (int t = 0; t < af.num_elements; t++) af.x[t] = wmma::__float_to_tf32(af.x[t]);
                    wmma::mma_sync(oacc[i], af, bf, oacc[i]);
                }
            }
#pragma unroll
            for (int i = 0; i < 2; i++)
                wmma::store_matrix_sync(o_s + (wm * 32 + i * 16) * ALD + wn * 16,
                                        oacc[i], ALD, wmma::mem_row_major);
        }
        __syncthreads();

        // acc = acc * alpha[r] + O_chunk
#pragma unroll
        for (int p = 0; p < 4; p++) {
            int r = tr + p * 16;
            float a = al_s[r];
            float4 ac = *(float4*)(accs + r * ACCLD + tc);
            float4 oc = *(float4*)(o_s + r * ALD + tc);
            ac.x = ac.x * a + oc.x; ac.y = ac.y * a + oc.y;
            ac.z = ac.z * a + oc.z; ac.w = ac.w * a + oc.w;
            *(float4*)(accs + r * ACCLD + tc) = ac;
        }
        __syncthreads();
    }

    // final: out[b, q0+r, h*64 + c] = acc / l
#pragma unroll
    for (int p = 0; p < 4; p++) {
        int r = tr + p * 16;
        float inv = 1.0f / l_s[r];
        float4 ac = *(float4*)(accs + r * ACCLD + tc);
        ac.x *= inv; ac.y *= inv; ac.z *= inv; ac.w *= inv;
        size_t o = ((size_t)(b * SEQ + q0 + r)) * DMODEL + h * HDIM + tc;
        *(float4*)(out + o) = ac;
    }
}

#define SMEM_ATTN ((5 * 64 * ALD + 64 * ACCLD + 3 * 64) * (int)sizeof(float))  // 110336

// ============================================================================
// LayerNorm over D=1024. One block per row, 256 threads x float4.
// ============================================================================
__global__ __launch_bounds__(256)
void ln_kernel(const float* __restrict__ x, const float* __restrict__ gw,
               const float* __restrict__ bw, float* __restrict__ out)
{
    __shared__ float red[16];
    __shared__ float stats[2];
    const int row = blockIdx.x;
    const int tid = threadIdx.x;
    const float* xr = x + (size_t)row * DMODEL;

    float4 xv = *(const float4*)(xr + tid * 4);
    float s  = xv.x + xv.y + xv.z + xv.w;
    float s2 = xv.x * xv.x + xv.y * xv.y + xv.z * xv.z + xv.w * xv.w;
#pragma unroll
    for (int o = 16; o > 0; o >>= 1) {
        s  += __shfl_xor_sync(0xffffffffu, s, o);
        s2 += __shfl_xor_sync(0xffffffffu, s2, o);
    }
    if ((tid & 31) == 0) { red[tid >> 5] = s; red[8 + (tid >> 5)] = s2; }
    __syncthreads();
    if (tid == 0) {
        float ts = 0.f, ts2 = 0.f;
#pragma unroll
        for (int i = 0; i < 8; i++) { ts += red[i]; ts2 += red[8 + i]; }
        float mu  = ts * (1.0f / DMODEL);
        float var = ts2 * (1.0f / DMODEL) - mu * mu;
        stats[0] = mu;
        stats[1] = rsqrtf(var + 1e-5f);
    }
    __syncthreads();
    float mu = stats[0], rstd = stats[1];
    float4 gv = *(const float4*)(gw + tid * 4);
    float4 bv = *(const float4*)(bw + tid * 4);
    float4 ov;
    ov.x = (xv.x - mu) * rstd * gv.x + bv.x;
    ov.y = (xv.y - mu) * rstd * gv.y + bv.y;
    ov.z = (xv.z - mu) * rstd * gv.z + bv.z;
    ov.w = (xv.w - mu) * rstd * gv.w + bv.w;
    *(float4*)(out + (size_t)row * DMODEL + tid * 4) = ov;
}

// ============================================================================
extern "C" void kernel_launch(void* const* d_in, const int* in_sizes, int n_in,
                              void* d_out, int out_size)
{
    const float* src = (const float*)d_in[0];
    const float* wq  = (const float*)d_in[1];
    const float* bq  = (const float*)d_in[2];
    const float* wk  = (const float*)d_in[3];
    const float* bk  = (const float*)d_in[4];
    const float* wv  = (const float*)d_in[5];
    const float* bv  = (const float*)d_in[6];
    const float* w1  = (const float*)d_in[7];
    const float* b1  = (const float*)d_in[8];
    const float* w2  = (const float*)d_in[9];
    const float* b2  = (const float*)d_in[10];
    const float* g1  = (const float*)d_in[11];
    const float* be1 = (const float*)d_in[12];
    const float* g2  = (const float*)d_in[13];
    const float* be2 = (const float*)d_in[14];
    float* out = (float*)d_out;

    cudaFuncSetAttribute(attn_kernel, cudaFuncAttributeMaxDynamicSharedMemorySize, SMEM_ATTN);

    float *q, *k, *v, *attn, *xln, *hb, *y;
    cudaGetSymbolAddress((void**)&q,    g_q);
    cudaGetSymbolAddress((void**)&k,    g_k);
    cudaGetSymbolAddress((void**)&v,    g_v);
    cudaGetSymbolAddress((void**)&attn, g_attn);
    cudaGetSymbolAddress((void**)&xln,  g_xln);
    cudaGetSymbolAddress((void**)&hb,   g_h);
    cudaGetSymbolAddress((void**)&y,    g_y);

    dim3 gQKV(DMODEL / GBN, MROWS / GBM);          // (16, 128)
    gemm_tn<0><<<gQKV, 256>>>(src, wq, bq, nullptr, q, DMODEL, DMODEL);
    gemm_tn<0><<<gQKV, 256>>>(src, wk, bk, nullptr, k, DMODEL, DMODEL);
    gemm_tn<0><<<gQKV, 256>>>(src, wv, bv, nullptr, v, DMODEL, DMODEL);

    attn_kernel<<<BATCH * NHEAD * (SEQ / 64), 256, SMEM_ATTN>>>(q, k, v, attn);

    ln_kernel<<<MROWS, 256>>>(attn, g1, be1, xln);

    dim3 gF1(DFF / GBN, MROWS / GBM);              // (64, 128)
    gemm_tn<1><<<gF1, 256>>>(xln, w1, b1, nullptr, hb, DMODEL, DFF);

    dim3 gF2(DMODEL / GBN, MROWS / GBM);           // (16, 128)
    gemm_tn<2><<<gF2, 256>>>(hb, w2, b2, xln, y, DFF, DMODEL);

    ln_kernel<<<MROWS, 256>>>(y, g2, be2, out);
}

// round 5
// speedup vs baseline: 1.0965x; 1.0965x over previous
#include <cuda_runtime.h>
#include <cuda_bf16.h>
#include <mma.h>
#include <cstdint>

using namespace nvcuda;

// Problem constants
#define BATCH  4
#define SEQ    4096
#define DMODEL 1024
#define NHEAD  16
#define HDIM   64
#define DFF    4096
#define WIN    512
#define MROWS  (BATCH*SEQ)          // 16384

// ---------------- scratch (device globals; no allocations allowed) ----------
static __device__ float g_q   [(size_t)MROWS * DMODEL];
static __device__ float g_k   [(size_t)MROWS * DMODEL];
static __device__ float g_v   [(size_t)MROWS * DMODEL];
static __device__ float g_attn[(size_t)MROWS * DMODEL];
static __device__ float g_xln [(size_t)MROWS * DMODEL];
static __device__ float g_h   [(size_t)MROWS * DFF];
static __device__ float g_y   [(size_t)MROWS * DMODEL];

__device__ __forceinline__ void cp_async16(float* dst, const float* src) {
    unsigned int d = (unsigned int)__cvta_generic_to_shared(dst);
    asm volatile("cp.async.cg.shared.global [%0], [%1], 16;\n" :: "r"(d), "l"(src));
}

// ============================================================================
// TN GEMM: C[M,N] = A[M,K] @ W[N,K]^T (+ epilogue), cp.async double-buffered.
//   MODE 0: +bias, scatter to [B,H,S,d] (QKV)
//   MODE 1: +bias, ReLU (FFN1)
//   MODE 2: +bias, +extra residual (FFN2)
// 256 threads = 8 warps as 2(m) x 4(n); warp tile 64x32 (4x2 m16n16k8 frags).
// Tile: BM=128, BN=128, BK=32. TF32 in, fp32 accum.
// ============================================================================
#define GBM 128
#define GBN 128
#define GBK 32
#define GLDA 40                 // padded k-stride (floats)
#define GSTAGE (2 * 128 * GLDA) // floats per stage (A then W)
#define GLDC 132
#define GEMM_SMEM (2 * GSTAGE * (int)sizeof(float))  // 81920 B

template <int MODE>
__global__ __launch_bounds__(256, 2)
void gemm_tn(const float* __restrict__ A, const float* __restrict__ W,
             const float* __restrict__ bias, const float* __restrict__ extra,
             float* __restrict__ out, int K, int N)
{
    extern __shared__ float sm[];

    const int tid = threadIdx.x;
    const int wid = tid >> 5;
    const int wm  = wid >> 2;   // 0..1
    const int wn  = wid & 3;    // 0..3

    wmma::fragment<wmma::accumulator, 16, 16, 8, float> acc[4][2];
#pragma unroll
    for (int i = 0; i < 4; i++)
#pragma unroll
        for (int j = 0; j < 2; j++)
            wmma::fill_fragment(acc[i][j], 0.0f);

    const float* Ablk = A + (size_t)blockIdx.y * GBM * K;
    const float* Wblk = W + (size_t)blockIdx.x * GBN * K;

    const int lr = tid >> 3;          // 0..31
    const int lc = (tid & 7) << 2;    // 0..28 step 4

    const int T = K / GBK;

    // stage loader: A[128x32] + W[128x32] via cp.async, one commit group
    auto load_stage = [&](int s, int kt) {
        float* As = sm + s * GSTAGE;
        float* Ws = As + 128 * GLDA;
#pragma unroll
        for (int p = 0; p < 4; p++) {
            int r = lr + p * 32;
            cp_async16(As + r * GLDA + lc, Ablk + (size_t)r * K + kt + lc);
            cp_async16(Ws + r * GLDA + lc, Wblk + (size_t)r * K + kt + lc);
        }
        asm volatile("cp.async.commit_group;\n");
    };

    load_stage(0, 0);

    for (int t = 0; t < T; t++) {
        const int cur = t & 1;
        if (t + 1 < T) {
            load_stage(cur ^ 1, (t + 1) * GBK);
            asm volatile("cp.async.wait_group 1;\n");
        } else {
            asm volatile("cp.async.wait_group 0;\n");
        }
        __syncthreads();

        const float* As = sm + cur * GSTAGE;
        const float* Ws = As + 128 * GLDA;
#pragma unroll
        for (int kk = 0; kk < GBK; kk += 8) {
            wmma::fragment<wmma::matrix_a, 16, 16, 8, wmma::precision::tf32, wmma::row_major> af[4];
            wmma::fragment<wmma::matrix_b, 16, 16, 8, wmma::precision::tf32, wmma::col_major> bf[2];
#pragma unroll
            for (int i = 0; i < 4; i++) {
                wmma::load_matrix_sync(af[i], As + (wm * 64 + i * 16) * GLDA + kk, GLDA);
#pragma unroll
                for (int e = 0; e < af[i].num_elements; e++)
                    af[i].x[e] = wmma::__float_to_tf32(af[i].x[e]);
            }
#pragma unroll
            for (int j = 0; j < 2; j++) {
                wmma::load_matrix_sync(bf[j], Ws + (wn * 32 + j * 16) * GLDA + kk, GLDA);
#pragma unroll
                for (int e = 0; e < bf[j].num_elements; e++)
                    bf[j].x[e] = wmma::__float_to_tf32(bf[j].x[e]);
            }
#pragma unroll
            for (int i = 0; i < 4; i++)
#pragma unroll
                for (int j = 0; j < 2; j++)
                    wmma::mma_sync(acc[i][j], af[i], bf[j], acc[i][j]);
        }
        __syncthreads();
    }

    // stage C through smem (aliases the pipeline buffers; loop-end sync done)
    float* Cs = sm;
#pragma unroll
    for (int i = 0; i < 4; i++)
#pragma unroll
        for (int j = 0; j < 2; j++)
            wmma::store_matrix_sync(Cs + (wm * 64 + i * 16) * GLDC + wn * 32 + j * 16,
                                    acc[i][j], GLDC, wmma::mem_row_major);
    __syncthreads();

    const int m0 = blockIdx.y * GBM;
    const int n0 = blockIdx.x * GBN;
    const int er = tid >> 5;           // 0..7
    const int ec = (tid & 31) << 2;    // 0..124 step 4

#pragma unroll
    for (int p = 0; p < 16; p++) {
        int r = er + p * 8;
        int m = m0 + r;
        float4 c = *(float4*)(Cs + r * GLDC + ec);
        float4 bb = *(const float4*)(bias + n0 + ec);
        c.x += bb.x; c.y += bb.y; c.z += bb.z; c.w += bb.w;
        if constexpr (MODE == 1) {
            c.x = fmaxf(c.x, 0.f); c.y = fmaxf(c.y, 0.f);
            c.z = fmaxf(c.z, 0.f); c.w = fmaxf(c.w, 0.f);
        }
        if constexpr (MODE == 2) {
            float4 e = *(const float4*)(extra + (size_t)m * N + n0 + ec);
            c.x += e.x; c.y += e.y; c.z += e.z; c.w += e.w;
        }
        if constexpr (MODE == 0) {
            int bi = m >> 12;          // /SEQ
            int s  = m & (SEQ - 1);
            int n  = n0 + ec;
            int h  = n >> 6;           // /HDIM
            int dd = n & (HDIM - 1);
            size_t o = (((size_t)bi * NHEAD + h) * SEQ + s) * HDIM + dd;
            *(float4*)(out + o) = c;
        } else {
            *(float4*)(out + (size_t)m * N + n0 + ec) = c;
        }
    }
}

// ============================================================================
// Windowed causal flash attention, v2:
//  - Q fragments live in registers (loaded from gmem once, scaled)
//  - no O staging buffer: accs scaled by alpha in softmax pass, then PV
//    accumulates directly into accs via accumulator-fragment load
// Block = (b, h, 64-row q chunk), 256 threads = 8 warps as 2(m) x 4(n).
// ============================================================================
#define ALD 72
#define ACCLD 68
#define ATTN_SMEM ((3 * 64 * ALD + 64 * ACCLD + 2 * 64) * (int)sizeof(float))

__global__ __launch_bounds__(256, 2)
void attn_kernel(const float* __restrict__ q, const float* __restrict__ k,
                 const float* __restrict__ v, float* __restrict__ out)
{
    const int idx = blockIdx.x;
    const int qc = idx & 7;
    const int w  = (idx >> 3) & 7;
    const int h  = (idx >> 6) & 15;
    const int b  = idx >> 10;

    extern __shared__ float sm[];
    float* k_s  = sm;                  // 64*ALD
    float* v_s  = k_s + 64 * ALD;
    float* s_s  = v_s + 64 * ALD;
    float* accs = s_s + 64 * ALD;      // 64*ACCLD
    float* m_s  = accs + 64 * ACCLD;   // 64
    float* l_s  = m_s + 64;            // 64

    const int tid = threadIdx.x;
    const int wid = tid >> 5;
    const int wm  = wid & 1;    // 0..1 (32 rows)
    const int wn  = wid >> 1;   // 0..3 (16 cols)
    const size_t headbase = ((size_t)(b * NHEAD + h)) * SEQ * HDIM;
    const int q0 = w * WIN + qc * 64;

    const int tr = tid >> 4;           // 0..15
    const int tc = (tid & 15) << 2;    // 0..60 step 4

    // preload Q fragments from GLOBAL into registers, scaled by d^-0.5
    wmma::fragment<wmma::matrix_a, 16, 16, 8, wmma::precision::tf32, wmma::row_major> a_q[2][8];
    {
        const float* qg = q + headbase + (size_t)q0 * HDIM;
#pragma unroll
        for (int i = 0; i < 2; i++)
#pragma unroll
            for (int ks = 0; ks < 8; ks++) {
                wmma::load_matrix_sync(a_q[i][ks],
                                       qg + (size_t)(wm * 32 + i * 16) * HDIM + ks * 8, HDIM);
#pragma unroll
                for (int e = 0; e < a_q[i][ks].num_elements; e++)
                    a_q[i][ks].x[e] = wmma::__float_to_tf32(a_q[i][ks].x[e] * 0.125f);
            }
    }

    // init acc / m / l
#pragma unroll
    for (int p = 0; p < 4; p++) {
        int r = tr + p * 16;
        *(float4*)(accs + r * ACCLD + tc) = make_float4(0.f, 0.f, 0.f, 0.f);
    }
    if (tid < 64) { m_s[tid] = -1e30f; l_s[tid] = 0.f; }

    const int kstart = (w == 0) ? 0 : (w - 1) * WIN;
    const int kend   = q0 + 64;

    for (int kc = kstart; kc < kend; kc += 64) {
        __syncthreads();   // S0: prev PV (reads v_s/s_s, writes accs) complete

        const float* kg = k + headbase + (size_t)kc * HDIM;
        const float* vg = v + headbase + (size_t)kc * HDIM;
#pragma unroll
        for (int p = 0; p < 4; p++) {
            int r = tr + p * 16;
            *(float4*)(k_s + r * ALD + tc) = *(const float4*)(kg + r * HDIM + tc);
            *(float4*)(v_s + r * ALD + tc) = *(const float4*)(vg + r * HDIM + tc);
        }
        __syncthreads();   // S1: k/v ready

        // S = q @ K^T (64x64): each warp 32 rows x 16 cols
        {
            wmma::fragment<wmma::accumulator, 16, 16, 8, float> sacc[2];
#pragma unroll
            for (int i = 0; i < 2; i++) wmma::fill_fragment(sacc[i], 0.0f);
#pragma unroll
            for (int ks = 0; ks < 8; ks++) {
                wmma::fragment<wmma::matrix_b, 16, 16, 8, wmma::precision::tf32, wmma::col_major> bf;
                wmma::load_matrix_sync(bf, k_s + (wn * 16) * ALD + ks * 8, ALD);
#pragma unroll
                for (int e = 0; e < bf.num_elements; e++)
                    bf.x[e] = wmma::__float_to_tf32(bf.x[e]);
#pragma unroll
                for (int i = 0; i < 2; i++)
                    wmma::mma_sync(sacc[i], a_q[i][ks], bf, sacc[i]);
            }
#pragma unroll
            for (int i = 0; i < 2; i++)
                wmma::store_matrix_sync(s_s + (wm * 32 + i * 16) * ALD + wn * 16,
                                        sacc[i], ALD, wmma::mem_row_major);
        }
        __syncthreads();   // S2: scores ready

        // online softmax (4 lanes/row x 16 cols) + scale accs by alpha
        {
            const bool diag = (kc == q0);
            const int r  = tid >> 2;           // 0..63
            const int c0 = (tid & 3) << 4;     // 0,16,32,48
            float* srow = s_s + r * ALD + c0;
            float mloc = -1e30f;
            if (diag) {
#pragma unroll
                for (int t = 0; t < 16; t++) {
                    float sv = srow[t];
                    if (c0 + t > r) sv = -1e30f;
                    srow[t] = sv;
                    mloc = fmaxf(mloc, sv);
                }
            } else {
#pragma unroll
                for (int t = 0; t < 16; t++) mloc = fmaxf(mloc, srow[t]);
            }
            mloc = fmaxf(mloc, __shfl_xor_sync(0xffffffffu, mloc, 1));
            mloc = fmaxf(mloc, __shfl_xor_sync(0xffffffffu, mloc, 2));
            float mold = m_s[r];
            float mnew = fmaxf(mold, mloc);
            float ssum = 0.f;
#pragma unroll
            for (int t = 0; t < 16; t++) {
                float pz = __expf(srow[t] - mnew);
                srow[t] = pz;
                ssum += pz;
            }
            ssum += __shfl_xor_sync(0xffffffffu, ssum, 1);
            ssum += __shfl_xor_sync(0xffffffffu, ssum, 2);
            float alpha = __expf(mold - mnew);   // 0 on first chunk
            if ((tid & 3) == 0) {
                m_s[r] = mnew;
                l_s[r] = l_s[r] * alpha + ssum;
            }
            // rescale accumulator rows in-place
            float* arow = accs + r * ACCLD + c0;
#pragma unroll
            for (int t = 0; t < 4; t++) {
                float4 a4 = *(float4*)(arow + t * 4);
                a4.x *= alpha; a4.y *= alpha; a4.z *= alpha; a4.w *= alpha;
                *(float4*)(arow + t * 4) = a4;
            }
        }
        __syncthreads();   // S3: P and scaled accs ready

        // accs += P @ V : load acc fragment from smem, accumulate, store back
        {
            wmma::fragment<wmma::accumulator, 16, 16, 8, float> oacc[2];
#pragma unroll
            for (int i = 0; i < 2; i++)
                wmma::load_matrix_sync(oacc[i],
                                       accs + (wm * 32 + i * 16) * ACCLD + wn * 16,
                                       ACCLD, wmma::mem_row_major);
#pragma unroll
            for (int ks = 0; ks < 8; ks++) {
                wmma::fragment<wmma::matrix_b, 16, 16, 8, wmma::precision::tf32, wmma::row_major> bf;
                wmma::load_matrix_sync(bf, v_s + (ks * 8) * ALD + wn * 16, ALD);
#pragma unroll
                for (int e = 0; e < bf.num_elements; e++)
                    bf.x[e] = wmma::__float_to_tf32(bf.x[e]);
#pragma unroll
                for (int i = 0; i < 2; i++) {
                    wmma::fragment<wmma::matrix_a, 16, 16, 8, wmma::precision::tf32, wmma::row_major> af;
                    wmma::load_matrix_sync(af, s_s + (wm * 32 + i * 16) * ALD + ks * 8, ALD);
#pragma unroll
                    for (int e = 0; e < af.num_elements; e++)
                        af.x[e] = wmma::__float_to_tf32(af.x[e]);
                    wmma::mma_sync(oacc[i], af, bf, oacc[i]);
                }
            }
#pragma unroll
            for (int i = 0; i < 2; i++)
                wmma::store_matrix_sync(accs + (wm * 32 + i * 16) * ACCLD + wn * 16,
                                        oacc[i], ACCLD, wmma::mem_row_major);
        }
    }
    __syncthreads();

    // out[b, q0+r, h*64 + c] = accs / l
#pragma unroll
    for (int p = 0; p < 4; p++) {
        int r = tr + p * 16;
        float inv = 1.0f / l_s[r];
        float4 ac = *(float4*)(accs + r * ACCLD + tc);
        ac.x *= inv; ac.y *= inv; ac.z *= inv; ac.w *= inv;
        size_t o = ((size_t)(b * SEQ + q0 + r)) * DMODEL + h * HDIM + tc;
        *(float4*)(out + o) = ac;
    }
}

// ============================================================================
// LayerNorm over D=1024. One block per row, 256 threads x float4.
// ============================================================================
__global__ __launch_bounds__(256)
void ln_kernel(const float* __restrict__ x, const float* __restrict__ gw,
               const float* __restrict__ bw, float* __restrict__ out)
{
    __shared__ float red[16];
    __shared__ float stats[2];
    const int row = blockIdx.x;
    const int tid = threadIdx.x;
    const float* xr = x + (size_t)row * DMODEL;

    float4 xv = *(const float4*)(xr + tid * 4);
    float s  = xv.x + xv.y + xv.z + xv.w;
    float s2 = xv.x * xv.x + xv.y * xv.y + xv.z * xv.z + xv.w * xv.w;
#pragma unroll
    for (int o = 16; o > 0; o >>= 1) {
        s  += __shfl_xor_sync(0xffffffffu, s, o);
        s2 += __shfl_xor_sync(0xffffffffu, s2, o);
    }
    if ((tid & 31) == 0) { red[tid >> 5] = s; red[8 + (tid >> 5)] = s2; }
    __syncthreads();
    if (tid == 0) {
        float ts = 0.f, ts2 = 0.f;
#pragma unroll
        for (int i = 0; i < 8; i++) { ts += red[i]; ts2 += red[8 + i]; }
        float mu  = ts * (1.0f / DMODEL);
        float var = ts2 * (1.0f / DMODEL) - mu * mu;
        stats[0] = mu;
        stats[1] = rsqrtf(var + 1e-5f);
    }
    __syncthreads();
    float mu = stats[0], rstd = stats[1];
    float4 gv = *(const float4*)(gw + tid * 4);
    float4 bv = *(const float4*)(bw + tid * 4);
    float4 ov;
    ov.x = (xv.x - mu) * rstd * gv.x + bv.x;
    ov.y = (xv.y - mu) * rstd * gv.y + bv.y;
    ov.z = (xv.z - mu) * rstd * gv.z + bv.z;
    ov.w = (xv.w - mu) * rstd * gv.w + bv.w;
    *(float4*)(out + (size_t)row * DMODEL + tid * 4) = ov;
}

// ============================================================================
extern "C" void kernel_launch(void* const* d_in, const int* in_sizes, int n_in,
                              void* d_out, int out_size)
{
    const float* src = (const float*)d_in[0];
    const float* wq  = (const float*)d_in[1];
    const float* bq  = (const float*)d_in[2];
    const float* wk  = (const float*)d_in[3];
    const float* bk  = (const float*)d_in[4];
    const float* wv  = (const float*)d_in[5];
    const float* bv  = (const float*)d_in[6];
    const float* w1  = (const float*)d_in[7];
    const float* b1  = (const float*)d_in[8];
    const float* w2  = (const float*)d_in[9];
    const float* b2  = (const float*)d_in[10];
    const float* g1  = (const float*)d_in[11];
    const float* be1 = (const float*)d_in[12];
    const float* g2  = (const float*)d_in[13];
    const float* be2 = (const float*)d_in[14];
    float* out = (float*)d_out;

    cudaFuncSetAttribute(gemm_tn<0>, cudaFuncAttributeMaxDynamicSharedMemorySize, GEMM_SMEM);
    cudaFuncSetAttribute(gemm_tn<1>, cudaFuncAttributeMaxDynamicSharedMemorySize, GEMM_SMEM);
    cudaFuncSetAttribute(gemm_tn<2>, cudaFuncAttributeMaxDynamicSharedMemorySize, GEMM_SMEM);
    cudaFuncSetAttribute(attn_kernel, cudaFuncAttributeMaxDynamicSharedMemorySize, ATTN_SMEM);

    float *q, *k, *v, *attn, *xln, *hb, *y;
    cudaGetSymbolAddress((void**)&q,    g_q);
    cudaGetSymbolAddress((void**)&k,    g_k);
    cudaGetSymbolAddress((void**)&v,    g_v);
    cudaGetSymbolAddress((void**)&attn, g_attn);
    cudaGetSymbolAddress((void**)&xln,  g_xln);
    cudaGetSymbolAddress((void**)&hb,   g_h);
    cudaGetSymbolAddress((void**)&y,    g_y);

    dim3 gQKV(DMODEL / GBN, MROWS / GBM);          // (8, 128)
    gemm_tn<0><<<gQKV, 256, GEMM_SMEM>>>(src, wq, bq, nullptr, q, DMODEL, DMODEL);
    gemm_tn<0><<<gQKV, 256, GEMM_SMEM>>>(src, wk, bk, nullptr, k, DMODEL, DMODEL);
    gemm_tn<0><<<gQKV, 256, GEMM_SMEM>>>(src, wv, bv, nullptr, v, DMODEL, DMODEL);

    attn_kernel<<<BATCH * NHEAD * (SEQ / 64), 256, ATTN_SMEM>>>(q, k, v, attn);

    ln_kernel<<<MROWS, 256>>>(attn, g1, be1, xln);

    dim3 gF1(DFF / GBN, MROWS / GBM);              // (32, 128)
    gemm_tn<1><<<gF1, 256, GEMM_SMEM>>>(xln, w1, b1, nullptr, hb, DMODEL, DFF);

    dim3 gF2(DMODEL / GBN, MROWS / GBM);           // (8, 128)
    gemm_tn<2><<<gF2, 256, GEMM_SMEM>>>(hb, w2, b2, xln, y, DFF, DMODEL);

    ln_kernel<<<MROWS, 256>>>(y, g2, be2, out);
}

// round 7
// speedup vs baseline: 1.1715x; 1.0684x over previous
#include <cuda_runtime.h>
#include <cuda_bf16.h>
#include <mma.h>
#include <cstdint>

using namespace nvcuda;

// Problem constants
#define BATCH  4
#define SEQ    4096
#define DMODEL 1024
#define NHEAD  16
#define HDIM   64
#define DFF    4096
#define WIN    512
#define MROWS  (BATCH*SEQ)          // 16384

// ---------------- scratch (device globals; no allocations allowed) ----------
static __device__ float g_q   [(size_t)MROWS * DMODEL];
static __device__ float g_k   [(size_t)MROWS * DMODEL];
static __device__ float g_v   [(size_t)MROWS * DMODEL];
static __device__ float g_attn[(size_t)MROWS * DMODEL];
static __device__ float g_xln [(size_t)MROWS * DMODEL];
static __device__ float g_h   [(size_t)MROWS * DFF];
static __device__ float g_y   [(size_t)MROWS * DMODEL];
// tf32-rounded copies
static __device__ float g_srcr[(size_t)MROWS * DMODEL];
static __device__ float g_wqr [(size_t)DMODEL * DMODEL];
static __device__ float g_wkr [(size_t)DMODEL * DMODEL];
static __device__ float g_wvr [(size_t)DMODEL * DMODEL];
static __device__ float g_w1r [(size_t)DFF * DMODEL];
static __device__ float g_w2r [(size_t)DMODEL * DFF];

__device__ __forceinline__ float tf32r(float x) {
    float y;
    asm("cvt.rna.tf32.f32 %0, %1;" : "=f"(y) : "f"(x));
    return y;
}

__device__ __forceinline__ void cp_async16(float* dst, const float* src) {
    unsigned int d = (unsigned int)__cvta_generic_to_shared(dst);
    asm volatile("cp.async.cg.shared.global [%0], [%1], 16;\n" :: "r"(d), "l"(src));
}

// ============================================================================
// Elementwise tf32 rounding prepass: out[i] = round_tf32(in[i])
// ============================================================================
__global__ __launch_bounds__(256)
void round_kernel(const float* __restrict__ in, float* __restrict__ out, int n4)
{
    int i = blockIdx.x * 256 + threadIdx.x;
    if (i < n4) {
        float4 x = *(const float4*)(in + (size_t)i * 4);
        x.x = tf32r(x.x); x.y = tf32r(x.y); x.z = tf32r(x.z); x.w = tf32r(x.w);
        *(float4*)(out + (size_t)i * 4) = x;
    }
}

// ============================================================================
// TN GEMM: C[M,N] = A[M,K] @ W[N,K]^T (+ epilogue), cp.async double-buffered.
// Inputs MUST already be tf32-rounded (no cvt in the mainloop).
//   MODE 0: +bias, scatter to [B,H,S,d], round outputs (QKV)
//   MODE 1: +bias, ReLU, round outputs (FFN1)
//   MODE 2: +bias, +extra residual (FFN2, no round)
// 256 threads = 8 warps as 2(m) x 4(n); warp tile 64x32 (4x2 m16n16k8 frags).
// Tile: BM=128, BN=128, BK=32.
// ============================================================================
#define GBM 128
#define GBN 128
#define GBK 32
#define GLDA 40                 // padded k-stride (floats)
#define GSTAGE (2 * 128 * GLDA) // floats per stage (A then W)
#define GLDC 132
#define GEMM_SMEM (2 * GSTAGE * (int)sizeof(float))  // 81920 B

template <int MODE>
__global__ __launch_bounds__(256, 2)
void gemm_tn(const float* __restrict__ A, const float* __restrict__ W,
             const float* __restrict__ bias, const float* __restrict__ extra,
             float* __restrict__ out, int K, int N)
{
    extern __shared__ float sm[];

    const int tid = threadIdx.x;
    const int wid = tid >> 5;
    const int wm  = wid >> 2;   // 0..1
    const int wn  = wid & 3;    // 0..3

    wmma::fragment<wmma::accumulator, 16, 16, 8, float> acc[4][2];
#pragma unroll
    for (int i = 0; i < 4; i++)
#pragma unroll
        for (int j = 0; j < 2; j++)
            wmma::fill_fragment(acc[i][j], 0.0f);

    const float* Ablk = A + (size_t)blockIdx.y * GBM * K;
    const float* Wblk = W + (size_t)blockIdx.x * GBN * K;

    const int lr = tid >> 3;          // 0..31
    const int lc = (tid & 7) << 2;    // 0..28 step 4

    const int T = K / GBK;

    auto load_stage = [&](int s, int kt) {
        float* As = sm + s * GSTAGE;
        float* Ws = As + 128 * GLDA;
#pragma unroll
        for (int p = 0; p < 4; p++) {
            int r = lr + p * 32;
            cp_async16(As + r * GLDA + lc, Ablk + (size_t)r * K + kt + lc);
            cp_async16(Ws + r * GLDA + lc, Wblk + (size_t)r * K + kt + lc);
        }
        asm volatile("cp.async.commit_group;\n");
    };

    load_stage(0, 0);

    for (int t = 0; t < T; t++) {
        const int cur = t & 1;
        if (t + 1 < T) {
            load_stage(cur ^ 1, (t + 1) * GBK);
            asm volatile("cp.async.wait_group 1;\n");
        } else {
            asm volatile("cp.async.wait_group 0;\n");
        }
        __syncthreads();

        const float* As = sm + cur * GSTAGE;
        const float* Ws = As + 128 * GLDA;
#pragma unroll
        for (int kk = 0; kk < GBK; kk += 8) {
            wmma::fragment<wmma::matrix_a, 16, 16, 8, wmma::precision::tf32, wmma::row_major> af[4];
            wmma::fragment<wmma::matrix_b, 16, 16, 8, wmma::precision::tf32, wmma::col_major> bf[2];
#pragma unroll
            for (int i = 0; i < 4; i++)
                wmma::load_matrix_sync(af[i], As + (wm * 64 + i * 16) * GLDA + kk, GLDA);
#pragma unroll
            for (int j = 0; j < 2; j++)
                wmma::load_matrix_sync(bf[j], Ws + (wn * 32 + j * 16) * GLDA + kk, GLDA);
#pragma unroll
            for (int i = 0; i < 4; i++)
#pragma unroll
                for (int j = 0; j < 2; j++)
                    wmma::mma_sync(acc[i][j], af[i], bf[j], acc[i][j]);
        }
        __syncthreads();
    }

    // stage C through smem
    float* Cs = sm;
#pragma unroll
    for (int i = 0; i < 4; i++)
#pragma unroll
        for (int j = 0; j < 2; j++)
            wmma::store_matrix_sync(Cs + (wm * 64 + i * 16) * GLDC + wn * 32 + j * 16,
                                    acc[i][j], GLDC, wmma::mem_row_major);
    __syncthreads();

    const int m0 = blockIdx.y * GBM;
    const int n0 = blockIdx.x * GBN;
    const int er = tid >> 5;           // 0..7
    const int ec = (tid & 31) << 2;    // 0..124 step 4

#pragma unroll
    for (int p = 0; p < 16; p++) {
        int r = er + p * 8;
        int m = m0 + r;
        float4 c = *(float4*)(Cs + r * GLDC + ec);
        float4 bb = *(const float4*)(bias + n0 + ec);
        c.x += bb.x; c.y += bb.y; c.z += bb.z; c.w += bb.w;
        if constexpr (MODE == 1) {
            c.x = tf32r(fmaxf(c.x, 0.f)); c.y = tf32r(fmaxf(c.y, 0.f));
            c.z = tf32r(fmaxf(c.z, 0.f)); c.w = tf32r(fmaxf(c.w, 0.f));
        }
        if constexpr (MODE == 2) {
            float4 e = *(const float4*)(extra + (size_t)m * N + n0 + ec);
            c.x += e.x; c.y += e.y; c.z += e.z; c.w += e.w;
        }
        if constexpr (MODE == 0) {
            c.x = tf32r(c.x); c.y = tf32r(c.y); c.z = tf32r(c.z); c.w = tf32r(c.w);
            int bi = m >> 12;          // /SEQ
            int s  = m & (SEQ - 1);
            int n  = n0 + ec;
            int h  = n >> 6;           // /HDIM
            int dd = n & (HDIM - 1);
            size_t o = (((size_t)bi * NHEAD + h) * SEQ + s) * HDIM + dd;
            *(float4*)(out + o) = c;
        } else {
            *(float4*)(out + (size_t)m * N + n0 + ec) = c;
        }
    }
}

// ============================================================================
// Windowed causal flash attention: register-Q, in-place accumulator.
// q/k/v are pre-rounded tf32 -> no cvt in matmul loops. P rounded at softmax.
// ============================================================================
#define ALD 72
#define ACCLD 68
#define ATTN_SMEM ((3 * 64 * ALD + 64 * ACCLD + 2 * 64) * (int)sizeof(float))

__global__ __launch_bounds__(256, 2)
void attn_kernel(const float* __restrict__ q, const float* __restrict__ k,
                 const float* __restrict__ v, float* __restrict__ out)
{
    const int idx = blockIdx.x;
    const int qc = idx & 7;
    const int w  = (idx >> 3) & 7;
    const int h  = (idx >> 6) & 15;
    const int b  = idx >> 10;

    extern __shared__ float sm[];
    float* k_s  = sm;
    float* v_s  = k_s + 64 * ALD;
    float* s_s  = v_s + 64 * ALD;
    float* accs = s_s + 64 * ALD;
    float* m_s  = accs + 64 * ACCLD;
    float* l_s  = m_s + 64;

    const int tid = threadIdx.x;
    const int wid = tid >> 5;
    const int wm  = wid & 1;
    const int wn  = wid >> 1;
    const size_t headbase = ((size_t)(b * NHEAD + h)) * SEQ * HDIM;
    const int q0 = w * WIN + qc * 64;

    const int tr = tid >> 4;
    const int tc = (tid & 15) << 2;

    // Q fragments from gmem; q is tf32-rounded and 0.125 scaling is exact.
    wmma::fragment<wmma::matrix_a, 16, 16, 8, wmma::precision::tf32, wmma::row_major> a_q[2][8];
    {
        const float* qg = q + headbase + (size_t)q0 * HDIM;
#pragma unroll
        for (int i = 0; i < 2; i++)
#pragma unroll
            for (int ks = 0; ks < 8; ks++) {
                wmma::load_matrix_sync(a_q[i][ks],
                                       qg + (size_t)(wm * 32 + i * 16) * HDIM + ks * 8, HDIM);
#pragma unroll
                for (int e = 0; e < a_q[i][ks].num_elements; e++)
                    a_q[i][ks].x[e] = a_q[i][ks].x[e] * 0.125f;
            }
    }

#pragma unroll
    for (int p = 0; p < 4; p++) {
        int r = tr + p * 16;
        *(float4*)(accs + r * ACCLD + tc) = make_float4(0.f, 0.f, 0.f, 0.f);
    }
    if (tid < 64) { m_s[tid] = -1e30f; l_s[tid] = 0.f; }

    const int kstart = (w == 0) ? 0 : (w - 1) * WIN;
    const int kend   = q0 + 64;

    for (int kc = kstart; kc < kend; kc += 64) {
        __syncthreads();

        const float* kg = k + headbase + (size_t)kc * HDIM;
        const float* vg = v + headbase + (size_t)kc * HDIM;
#pragma unroll
        for (int p = 0; p < 4; p++) {
            int r = tr + p * 16;
            *(float4*)(k_s + r * ALD + tc) = *(const float4*)(kg + r * HDIM + tc);
            *(float4*)(v_s + r * ALD + tc) = *(const float4*)(vg + r * HDIM + tc);
        }
        __syncthreads();

        // S = q @ K^T
        {
            wmma::fragment<wmma::accumulator, 16, 16, 8, float> sacc[2];
#pragma unroll
            for (int i = 0; i < 2; i++) wmma::fill_fragment(sacc[i], 0.0f);
#pragma unroll
            for (int ks = 0; ks < 8; ks++) {
                wmma::fragment<wmma::matrix_b, 16, 16, 8, wmma::precision::tf32, wmma::col_major> bf;
                wmma::load_matrix_sync(bf, k_s + (wn * 16) * ALD + ks * 8, ALD);
#pragma unroll
                for (int i = 0; i < 2; i++)
                    wmma::mma_sync(sacc[i], a_q[i][ks], bf, sacc[i]);
            }
#pragma unroll
            for (int i = 0; i < 2; i++)
                wmma::store_matrix_sync(s_s + (wm * 32 + i * 16) * ALD + wn * 16,
                                        sacc[i], ALD, wmma::mem_row_major);
        }
        __syncthreads();

        // online softmax; P written tf32-rounded
        {
            const bool diag = (kc == q0);
            const int r  = tid >> 2;
            const int c0 = (tid & 3) << 4;
            float* srow = s_s + r * ALD + c0;
            float mloc = -1e30f;
            if (diag) {
#pragma unroll
                for (int t = 0; t < 16; t++) {
                    float sv = srow[t];
                    if (c0 + t > r) sv = -1e30f;
                    srow[t] = sv;
                    mloc = fmaxf(mloc, sv);
                }
            } else {
#pragma unroll
                for (int t = 0; t < 16; t++) mloc = fmaxf(mloc, srow[t]);
            }
            mloc = fmaxf(mloc, __shfl_xor_sync(0xffffffffu, mloc, 1));
            mloc = fmaxf(mloc, __shfl_xor_sync(0xffffffffu, mloc, 2));
            float mold = m_s[r];
            float mnew = fmaxf(mold, mloc);
            float ssum = 0.f;
#pragma unroll
            for (int t = 0; t < 16; t++) {
                float pz = tf32r(__expf(srow[t] - mnew));
                srow[t] = pz;
                ssum += pz;
            }
            ssum += __shfl_xor_sync(0xffffffffu, ssum, 1);
            ssum += __shfl_xor_sync(0xffffffffu, ssum, 2);
            float alpha = __expf(mold - mnew);
            if ((tid & 3) == 0) {
                m_s[r] = mnew;
                l_s[r] = l_s[r] * alpha + ssum;
            }
            float* arow = accs + r * ACCLD + c0;
#pragma unroll
            for (int t = 0; t < 4; t++) {
                float4 a4 = *(float4*)(arow + t * 4);
                a4.x *= alpha; a4.y *= alpha; a4.z *= alpha; a4.w *= alpha;
                *(float4*)(arow + t * 4) = a4;
            }
        }
        __syncthreads();

        // accs += P @ V
        {
            wmma::fragment<wmma::accumulator, 16, 16, 8, float> oacc[2];
#pragma unroll
            for (int i = 0; i < 2; i++)
                wmma::load_matrix_sync(oacc[i],
                                       accs + (wm * 32 + i * 16) * ACCLD + wn * 16,
                                       ACCLD, wmma::mem_row_major);
#pragma unroll
            for (int ks = 0; ks < 8; ks++) {
                wmma::fragment<wmma::matrix_b, 16, 16, 8, wmma::precision::tf32, wmma::row_major> bf;
                wmma::load_matrix_sync(bf, v_s + (ks * 8) * ALD + wn * 16, ALD);
#pragma unroll
                for (int i = 0; i < 2; i++) {
                    wmma::fragment<wmma::matrix_a, 16, 16, 8, wmma::precision::tf32, wmma::row_major> af;
                    wmma::load_matrix_sync(af, s_s + (wm * 32 + i * 16) * ALD + ks * 8, ALD);
                    wmma::mma_sync(oacc[i], af, bf, oacc[i]);
                }
            }
#pragma unroll
            for (int i = 0; i < 2; i++)
                wmma::store_matrix_sync(accs + (wm * 32 + i * 16) * ACCLD + wn * 16,
                                        oacc[i], ACCLD, wmma::mem_row_major);
        }
    }
    __syncthreads();

#pragma unroll
    for (int p = 0; p < 4; p++) {
        int r = tr + p * 16;
        float inv = 1.0f / l_s[r];
        float4 ac = *(float4*)(accs + r * ACCLD + tc);
        ac.x *= inv; ac.y *= inv; ac.z *= inv; ac.w *= inv;
        size_t o = ((size_t)(b * SEQ + q0 + r)) * DMODEL + h * HDIM + tc;
        *(float4*)(out + o) = ac;
    }
}

// ============================================================================
// LayerNorm over D=1024. One block per row, 256 threads x float4.
// ROUND=1: output rounded to tf32 (feeds GEMMs).
// ============================================================================
template <int ROUND>
__global__ __launch_bounds__(256)
void ln_kernel(const float* __restrict__ x, const float* __restrict__ gw,
               const float* __restrict__ bw, float* __restrict__ out)
{
    __shared__ float red[16];
    __shared__ float stats[2];
    const int row = blockIdx.x;
    const int tid = threadIdx.x;
    const float* xr = x + (size_t)row * DMODEL;

    float4 xv = *(const float4*)(xr + tid * 4);
    float s  = xv.x + xv.y + xv.z + xv.w;
    float s2 = xv.x * xv.x + xv.y * xv.y + xv.z * xv.z + xv.w * xv.w;
#pragma unroll
    for (int o = 16; o > 0; o >>= 1) {
        s  += __shfl_xor_sync(0xffffffffu, s, o);
        s2 += __shfl_xor_sync(0xffffffffu, s2, o);
    }
    if ((tid & 31) == 0) { red[tid >> 5] = s; red[8 + (tid >> 5)] = s2; }
    __syncthreads();
    if (tid == 0) {
        float ts = 0.f, ts2 = 0.f;
#pragma unroll
        for (int i = 0; i < 8; i++) { ts += red[i]; ts2 += red[8 + i]; }
        float mu  = ts * (1.0f / DMODEL);
        float var = ts2 * (1.0f / DMODEL) - mu * mu;
        stats[0] = mu;
        stats[1] = rsqrtf(var + 1e-5f);
    }
    __syncthreads();
    float mu = stats[0], rstd = stats[1];
    float4 gv = *(const float4*)(gw + tid * 4);
    float4 bv = *(const float4*)(bw + tid * 4);
    float4 ov;
    ov.x = (xv.x - mu) * rstd * gv.x + bv.x;
    ov.y = (xv.y - mu) * rstd * gv.y + bv.y;
    ov.z = (xv.z - mu) * rstd * gv.z + bv.z;
    ov.w = (xv.w - mu) * rstd * gv.w + bv.w;
    if constexpr (ROUND == 1) {
        ov.x = tf32r(ov.x); ov.y = tf32r(ov.y); ov.z = tf32r(ov.z); ov.w = tf32r(ov.w);
    }
    *(float4*)(out + (size_t)row * DMODEL + tid * 4) = ov;
}

// ============================================================================
extern "C" void kernel_launch(void* const* d_in, const int* in_sizes, int n_in,
                              void* d_out, int out_size)
{
    const float* src = (const float*)d_in[0];
    const float* wq  = (const float*)d_in[1];
    const float* bq  = (const float*)d_in[2];
    const float* wk  = (const float*)d_in[3];
    const float* bk  = (const float*)d_in[4];
    const float* wv  = (const float*)d_in[5];
    const float* bv  = (const float*)d_in[6];
    const float* w1  = (const float*)d_in[7];
    const float* b1  = (const float*)d_in[8];
    const float* w2  = (const float*)d_in[9];
    const float* b2  = (const float*)d_in[10];
    const float* g1  = (const float*)d_in[11];
    const float* be1 = (const float*)d_in[12];
    const float* g2  = (const float*)d_in[13];
    const float* be2 = (const float*)d_in[14];
    float* out = (float*)d_out;

    cudaFuncSetAttribute(gemm_tn<0>, cudaFuncAttributeMaxDynamicSharedMemorySize, GEMM_SMEM);
    cudaFuncSetAttribute(gemm_tn<1>, cudaFuncAttributeMaxDynamicSharedMemorySize, GEMM_SMEM);
    cudaFuncSetAttribute(gemm_tn<2>, cudaFuncAttributeMaxDynamicSharedMemorySize, GEMM_SMEM);
    cudaFuncSetAttribute(attn_kernel, cudaFuncAttributeMaxDynamicSharedMemorySize, ATTN_SMEM);

    float *q, *k, *v, *attn, *xln, *hb, *y;
    float *srcr, *wqr, *wkr, *wvr, *w1r, *w2r;
    cudaGetSymbolAddress((void**)&q,    g_q);
    cudaGetSymbolAddress((void**)&k,    g_k);
    cudaGetSymbolAddress((void**)&v,    g_v);
    cudaGetSymbolAddress((void**)&attn, g_attn);
    cudaGetSymbolAddress((void**)&xln,  g_xln);
    cudaGetSymbolAddress((void**)&hb,   g_h);
    cudaGetSymbolAddress((void**)&y,    g_y);
    cudaGetSymbolAddress((void**)&srcr, g_srcr);
    cudaGetSymbolAddress((void**)&wqr,  g_wqr);
    cudaGetSymbolAddress((void**)&wkr,  g_wkr);
    cudaGetSymbolAddress((void**)&wvr,  g_wvr);
    cudaGetSymbolAddress((void**)&w1r,  g_w1r);
    cudaGetSymbolAddress((void**)&w2r,  g_w2r);

    // -------- tf32 rounding prepasses --------
    {
        int n4;
        n4 = MROWS * DMODEL / 4;
        round_kernel<<<(n4 + 255) / 256, 256>>>(src, srcr, n4);
        n4 = DMODEL * DMODEL / 4;
        round_kernel<<<(n4 + 255) / 256, 256>>>(wq, wqr, n4);
        round_kernel<<<(n4 + 255) / 256, 256>>>(wk, wkr, n4);
        round_kernel<<<(n4 + 255) / 256, 256>>>(wv, wvr, n4);
        n4 = DFF * DMODEL / 4;
        round_kernel<<<(n4 + 255) / 256, 256>>>(w1, w1r, n4);
        round_kernel<<<(n4 + 255) / 256, 256>>>(w2, w2r, n4);
    }

    dim3 gQKV(DMODEL / GBN, MROWS / GBM);          // (8, 128)
    gemm_tn<0><<<gQKV, 256, GEMM_SMEM>>>(srcr, wqr, bq, nullptr, q, DMODEL, DMODEL);
    gemm_tn<0><<<gQKV, 256, GEMM_SMEM>>>(srcr, wkr, bk, nullptr, k, DMODEL, DMODEL);
    gemm_tn<0><<<gQKV, 256, GEMM_SMEM>>>(srcr, wvr, bv, nullptr, v, DMODEL, DMODEL);

    attn_kernel<<<BATCH * NHEAD * (SEQ / 64), 256, ATTN_SMEM>>>(q, k, v, attn);

    ln_kernel<1><<<MROWS, 256>>>(attn, g1, be1, xln);

    dim3 gF1(DFF / GBN, MROWS / GBM);              // (32, 128)
    gemm_tn<1><<<gF1, 256, GEMM_SMEM>>>(xln, w1r, b1, nullptr, hb, DMODEL, DFF);

    dim3 gF2(DMODEL / GBN, MROWS / GBM);           // (8, 128)
    gemm_tn<2><<<gF2, 256, GEMM_SMEM>>>(hb, w2r, b2, xln, y, DFF, DMODEL);

    ln_kernel<0><<<MROWS, 256>>>(y, g2, be2, out);
}